// round 11
// baseline (speedup 1.0000x reference)
#include <cuda_runtime.h>
#include <cstdint>

#define N_NODES 100000
#define OUTW 68
typedef unsigned long long u64;

#define FB 152            // blocks (= SMs, 1 CTA/SM -> all co-resident)
#define FT 768            // threads per block
#define WARPS 24
#define NPW 4

__device__ float g_nsum[(size_t)N_NODES * 64];
__device__ float g_deg[N_NODES];
__device__ unsigned g_pmaskbits[3136];
__device__ int g_list[N_NODES];
__device__ int g_cnt;
__device__ unsigned g_bar_arrive = 0;
__device__ unsigned g_bar_gen = 0;

__device__ __forceinline__ u64 pack2(float a, float b) {
    u64 r; asm("mov.b64 %0, {%1, %2};" : "=l"(r) : "f"(a), "f"(b)); return r;
}
__device__ __forceinline__ void ffma2(u64& d, u64 a, u64 b) {
    asm("fma.rn.f32x2 %0, %1, %2, %3;" : "=l"(d) : "l"(a), "l"(b), "l"(d));
}
__device__ __forceinline__ float psum(u64 v) {
    float a, b;
    asm("mov.b64 {%0, %1}, %2;" : "=f"(a), "=f"(b) : "l"(v));
    return a + b;
}

// Software grid barrier: 152 co-resident blocks, generation-counted so it is
// reusable and graph-replay safe (arrive counter self-resets to 0).
__device__ __forceinline__ void grid_barrier() {
    __syncthreads();
    if (threadIdx.x == 0) {
        __threadfence();
        unsigned gen = *(volatile unsigned*)&g_bar_gen;
        unsigned arrived = atomicAdd(&g_bar_arrive, 1u);
        if (arrived == gridDim.x - 1) {
            g_bar_arrive = 0;
            __threadfence();
            atomicAdd(&g_bar_gen, 1u);
        } else {
            while (*(volatile unsigned*)&g_bar_gen == gen) {}
        }
        __threadfence();
    }
    __syncthreads();
}

// Ballot work redistribution: 4 jobs/iter, 8 lanes x 2 float4-chunks per job.
__device__ __forceinline__ void scatter_jobs(bool active, int tgt, int srcn,
                                             int lane,
                                             const float4* __restrict__ feat4,
                                             float4* nsum4) {
    unsigned m = __ballot_sync(0xffffffffu, active);
    int grp = lane >> 3;
    int c = lane & 7;
    while (m) {
        int b0 = -1, b1 = -1, b2 = -1, b3 = -1;
        b0 = __ffs(m) - 1; m &= m - 1;
        if (m) { b1 = __ffs(m) - 1; m &= m - 1; }
        if (m) { b2 = __ffs(m) - 1; m &= m - 1; }
        if (m) { b3 = __ffs(m) - 1; m &= m - 1; }
        int myb = (grp == 0) ? b0 : (grp == 1) ? b1 : (grp == 2) ? b2 : b3;
        int bb = (myb >= 0) ? myb : b0;
        int T = __shfl_sync(0xffffffffu, tgt,  bb);
        int S = __shfl_sync(0xffffffffu, srcn, bb);
        if (myb >= 0) {
            float4 v0 = __ldg(&feat4[(size_t)S * 16 + c]);
            float4 v1 = __ldg(&feat4[(size_t)S * 16 + c + 8]);
            asm volatile("red.global.add.v4.f32 [%0], {%1,%2,%3,%4};" ::
                         "l"(nsum4 + (size_t)T * 16 + c),
                         "f"(v0.x), "f"(v0.y), "f"(v0.z), "f"(v0.w) : "memory");
            asm volatile("red.global.add.v4.f32 [%0], {%1,%2,%3,%4};" ::
                         "l"(nsum4 + (size_t)T * 16 + c + 8),
                         "f"(v1.x), "f"(v1.y), "f"(v1.z), "f"(v1.w) : "memory");
            if (c == 0) atomicAdd(&g_deg[T], 1.f);
        }
    }
}

// ---- smem layout (floats) ----
#define OFF_W1   0          // u64[64][128] = 16384 floats
#define OFF_W2   16384      // u64[64][64]  = 8192
#define OFF_W3   24576      // u64[32][68]  = 4352
#define OFF_P1   28928      // u64[32][32]  = 2048
#define OFF_B1   30976
#define OFF_B2   31104
#define OFF_B3   31168
#define OFF_PB1  31236
#define OFF_P2   31268
#define OFF_PB2  31300
#define OFF_SCR  31304      // per-warp NPW*128 floats
#define SMEM_FLOATS (OFF_SCR + WARPS * NPW * 128)

__global__ void __launch_bounds__(FT, 1)
fused_kernel(const float* __restrict__ nf,
             const float* __restrict__ ops,
             const int* __restrict__ ei, int E,
             const float* __restrict__ W1, const float* __restrict__ b1,
             const float* __restrict__ W2, const float* __restrict__ b2,
             const float* __restrict__ W3, const float* __restrict__ b3,
             const float* __restrict__ P1, const float* __restrict__ pb1,
             const float* __restrict__ P2, const float* __restrict__ pb2,
             float* __restrict__ out) {
    extern __shared__ float sm[];
    const int tid = threadIdx.x;
    const int lane = tid & 31;
    const int gstride = gridDim.x * FT;

    // ================= Phase 0: weight staging (coalesced, K-paired) ======
    {
        const float4* W1_4 = reinterpret_cast<const float4*>(W1);
        u64* W1p = reinterpret_cast<u64*>(sm + OFF_W1);
        for (int idx = tid; idx < 2048; idx += FT) {
            int t = idx >> 5, jv = idx & 31;
            float4 a = W1_4[(2 * t) * 32 + jv];
            float4 b = W1_4[(2 * t + 1) * 32 + jv];
            ulonglong2* dst = reinterpret_cast<ulonglong2*>(W1p + t * 128 + 4 * jv);
            dst[0] = make_ulonglong2(pack2(a.x, b.x), pack2(a.y, b.y));
            dst[1] = make_ulonglong2(pack2(a.z, b.z), pack2(a.w, b.w));
        }
        const float4* W2_4 = reinterpret_cast<const float4*>(W2);
        u64* W2p = reinterpret_cast<u64*>(sm + OFF_W2);
        for (int idx = tid; idx < 1024; idx += FT) {
            int t = idx >> 4, jv = idx & 15;
            float4 a = W2_4[(2 * t) * 16 + jv];
            float4 b = W2_4[(2 * t + 1) * 16 + jv];
            ulonglong2* dst = reinterpret_cast<ulonglong2*>(W2p + t * 64 + 4 * jv);
            dst[0] = make_ulonglong2(pack2(a.x, b.x), pack2(a.y, b.y));
            dst[1] = make_ulonglong2(pack2(a.z, b.z), pack2(a.w, b.w));
        }
        u64* W3p = reinterpret_cast<u64*>(sm + OFF_W3);
        for (int idx = tid; idx < 2176; idx += FT) {
            int t = idx / 68, j = idx - t * 68;
            W3p[idx] = (j < 67)
                ? pack2(W3[(2 * t) * 67 + j], W3[(2 * t + 1) * 67 + j]) : 0ull;
        }
        const float4* P1_4 = reinterpret_cast<const float4*>(P1);
        u64* P1p = reinterpret_cast<u64*>(sm + OFF_P1);
        for (int idx = tid; idx < 256; idx += FT) {
            int t = idx >> 3, jv = idx & 7;
            float4 a = P1_4[(2 * t) * 8 + jv];
            float4 b = P1_4[(2 * t + 1) * 8 + jv];
            ulonglong2* dst = reinterpret_cast<ulonglong2*>(P1p + t * 32 + 4 * jv);
            dst[0] = make_ulonglong2(pack2(a.x, b.x), pack2(a.y, b.y));
            dst[1] = make_ulonglong2(pack2(a.z, b.z), pack2(a.w, b.w));
        }
        for (int i = tid; i < 128; i += FT) sm[OFF_B1 + i] = b1[i];
        for (int i = tid; i < 64;  i += FT) sm[OFF_B2 + i] = b2[i];
        for (int i = tid; i < 67;  i += FT) sm[OFF_B3 + i] = b3[i];
        for (int i = tid; i < 32;  i += FT) sm[OFF_PB1 + i] = pb1[i];
        for (int i = tid; i < 32;  i += FT) sm[OFF_P2 + i] = P2[i];
        if (tid == 0) sm[OFF_PB2] = pb2[0];
    }

    // ================= Phase 1: softmax gate + deg/nsum init ===============
    {
        int gid = blockIdx.x * FT + tid;
        if (gid == 0) g_cnt = 0;
        for (int base = blockIdx.x * FT; base < N_NODES; base += gstride) {
            int n = base + tid;
            bool msk = false;
            if (n < N_NODES) {
                float o0 = ops[n * 4 + 0], o1 = ops[n * 4 + 1];
                float o2 = ops[n * 4 + 2], o3 = ops[n * 4 + 3];
                float mx = fmaxf(fmaxf(o0, o1), fmaxf(o2, o3));
                float e0 = expf(o0 - mx), e1 = expf(o1 - mx);
                float e2 = expf(o2 - mx), e3 = expf(o3 - mx);
                float p0 = e0 / (e0 + e1 + e2 + e3);
                msk = (p0 > 0.5f);
                g_deg[n] = 0.f;
            }
            unsigned bits = __ballot_sync(0xffffffffu, msk);
            if (lane == 0 && (n & ~31) < N_NODES)
                g_pmaskbits[n >> 5] = bits;
            if (msk) {
                float4 z = make_float4(0.f, 0.f, 0.f, 0.f);
                float4* row = reinterpret_cast<float4*>(g_nsum) + (size_t)n * 16;
                #pragma unroll
                for (int c = 0; c < 16; c++) row[c] = z;
            }
        }
    }
    grid_barrier();

    // ================= Phase 2: gated edge scatter (1 thread/edge) =========
    {
        const float4* feat4 = reinterpret_cast<const float4*>(nf);
        float4* nsum4 = reinterpret_cast<float4*>(g_nsum);
        for (int base = blockIdx.x * FT; base < E; base += gstride) {
            int e = base + tid;
            bool v = e < E;
            int s = 0, d = 0;
            if (v) { s = __ldg(&ei[e]); d = __ldg(&ei[E + e]); }
            bool a0 = v && ((g_pmaskbits[s >> 5] >> (s & 31)) & 1);
            bool a1 = v && ((g_pmaskbits[d >> 5] >> (d & 31)) & 1);
            scatter_jobs(a0, s, d, lane, feat4, nsum4);   // tgt=s gets feat[d]
            scatter_jobs(a1, d, s, lane, feat4, nsum4);   // tgt=d gets feat[s]
        }
    }
    grid_barrier();

    // ================= Phase 3: compact active nodes =======================
    {
        for (int base = blockIdx.x * FT; base < N_NODES; base += gstride) {
            int n = base + tid;
            bool act = false;
            if (n < N_NODES)
                act = ((g_pmaskbits[n >> 5] >> (n & 31)) & 1) && (g_deg[n] > 0.f);
            unsigned m = __ballot_sync(0xffffffffu, act);
            int basep = 0;
            if (lane == 0 && m) basep = atomicAdd(&g_cnt, __popc(m));
            basep = __shfl_sync(0xffffffffu, basep, 0);
            if (act) g_list[basep + __popc(m & ((1u << lane) - 1))] = n;
        }
    }
    grid_barrier();

    // ================= Phase 4: MLP over active nodes (R10 core) ===========
    {
        int warpId = tid >> 5;
        float* buf = sm + OFF_SCR + warpId * (NPW * 128);
        float4* buf4 = reinterpret_cast<float4*>(buf);
        ulonglong2* bufp = reinterpret_cast<ulonglong2*>(buf);

        const ulonglong2* sW1p2 = reinterpret_cast<const ulonglong2*>(sm + OFF_W1);
        const ulonglong2* sW2p2 = reinterpret_cast<const ulonglong2*>(sm + OFF_W2);
        const u64*        sW3p  = reinterpret_cast<const u64*>(sm + OFF_W3);
        const u64*        sP1p  = reinterpret_cast<const u64*>(sm + OFF_P1);
        const float4*     sb1_4 = reinterpret_cast<const float4*>(sm + OFF_B1);

        const int cnt = *(volatile int*)&g_cnt;
        const int totalWarps = gridDim.x * WARPS;

        for (int g = blockIdx.x * WARPS + warpId; g * NPW < cnt; g += totalWarps) {
            int nn[NPW];
            bool valid[NPW];
            #pragma unroll
            for (int q = 0; q < NPW; q++) {
                int li = g * NPW + q;
                valid[q] = li < cnt;
                nn[q] = g_list[valid[q] ? li : g * NPW];
            }

            #pragma unroll
            for (int q = 0; q < NPW; q++) {
                int n = nn[q];
                float inv = 1.f / fmaxf(g_deg[n], 1.f);
                buf[q * 128 + lane]      = nf[(size_t)n * 64 + lane];
                buf[q * 128 + 32 + lane] = nf[(size_t)n * 64 + 32 + lane];
                buf[q * 128 + 64 + lane] = g_nsum[(size_t)n * 64 + lane] * inv;
                buf[q * 128 + 96 + lane] = g_nsum[(size_t)n * 64 + 32 + lane] * inv;
            }
            __syncwarp();

            // layer 1: 128 -> 128 relu (K-paired FFMA2)
            u64 a0[NPW], a1[NPW], a2[NPW], a3[NPW];
            {
                float4 bb = sb1_4[lane];
                u64 i0 = pack2(bb.x, 0.f), i1 = pack2(bb.y, 0.f);
                u64 i2 = pack2(bb.z, 0.f), i3 = pack2(bb.w, 0.f);
                #pragma unroll
                for (int q = 0; q < NPW; q++) {
                    a0[q] = i0; a1[q] = i1; a2[q] = i2; a3[q] = i3;
                }
            }
            #pragma unroll 4
            for (int i4 = 0; i4 < 32; i4++) {
                int t0 = 2 * i4, t1 = 2 * i4 + 1;
                ulonglong2 wA0 = sW1p2[t0 * 64 + 2 * lane];
                ulonglong2 wA1 = sW1p2[t0 * 64 + 2 * lane + 1];
                ulonglong2 wB0 = sW1p2[t1 * 64 + 2 * lane];
                ulonglong2 wB1 = sW1p2[t1 * 64 + 2 * lane + 1];
                #pragma unroll
                for (int q = 0; q < NPW; q++) {
                    ulonglong2 cp = bufp[q * 32 + i4];
                    ffma2(a0[q], wA0.x, cp.x); ffma2(a1[q], wA0.y, cp.x);
                    ffma2(a2[q], wA1.x, cp.x); ffma2(a3[q], wA1.y, cp.x);
                    ffma2(a0[q], wB0.x, cp.y); ffma2(a1[q], wB0.y, cp.y);
                    ffma2(a2[q], wB1.x, cp.y); ffma2(a3[q], wB1.y, cp.y);
                }
            }
            __syncwarp();
            #pragma unroll
            for (int q = 0; q < NPW; q++) {
                buf4[q * 32 + lane] = make_float4(
                    fmaxf(psum(a0[q]), 0.f), fmaxf(psum(a1[q]), 0.f),
                    fmaxf(psum(a2[q]), 0.f), fmaxf(psum(a3[q]), 0.f));
            }
            __syncwarp();

            // layer 2: 128 -> 64 relu
            u64 c0[NPW], c1[NPW];
            {
                u64 i0 = pack2(sm[OFF_B2 + 2 * lane], 0.f);
                u64 i1 = pack2(sm[OFF_B2 + 2 * lane + 1], 0.f);
                #pragma unroll
                for (int q = 0; q < NPW; q++) { c0[q] = i0; c1[q] = i1; }
            }
            #pragma unroll 4
            for (int i4 = 0; i4 < 32; i4++) {
                int t0 = 2 * i4, t1 = 2 * i4 + 1;
                ulonglong2 w0 = sW2p2[t0 * 32 + lane];
                ulonglong2 w1 = sW2p2[t1 * 32 + lane];
                #pragma unroll
                for (int q = 0; q < NPW; q++) {
                    ulonglong2 cp = bufp[q * 32 + i4];
                    ffma2(c0[q], w0.x, cp.x); ffma2(c1[q], w0.y, cp.x);
                    ffma2(c0[q], w1.x, cp.y); ffma2(c1[q], w1.y, cp.y);
                }
            }
            __syncwarp();
            #pragma unroll
            for (int q = 0; q < NPW; q++) {
                reinterpret_cast<float2*>(buf)[q * 64 + lane] = make_float2(
                    fmaxf(psum(c0[q]), 0.f), fmaxf(psum(c1[q]), 0.f));
            }
            __syncwarp();

            // layer 3: 64 -> 67
            u64 g0[NPW], g1[NPW], g2[NPW];
            {
                u64 i0 = pack2(sm[OFF_B3 + lane], 0.f);
                u64 i1 = pack2(sm[OFF_B3 + 32 + lane], 0.f);
                u64 i2 = (lane < 3) ? pack2(sm[OFF_B3 + 64 + lane], 0.f) : 0ull;
                #pragma unroll
                for (int q = 0; q < NPW; q++) { g0[q] = i0; g1[q] = i1; g2[q] = i2; }
            }
            #pragma unroll 4
            for (int i4 = 0; i4 < 16; i4++) {
                int t0 = 2 * i4, t1 = 2 * i4 + 1;
                u64 wa0 = sW3p[t0 * 68 + lane];
                u64 wa1 = sW3p[t0 * 68 + 32 + lane];
                u64 wa2 = (lane < 3) ? sW3p[t0 * 68 + 64 + lane] : 0ull;
                u64 wb0 = sW3p[t1 * 68 + lane];
                u64 wb1 = sW3p[t1 * 68 + 32 + lane];
                u64 wb2 = (lane < 3) ? sW3p[t1 * 68 + 64 + lane] : 0ull;
                #pragma unroll
                for (int q = 0; q < NPW; q++) {
                    ulonglong2 cp = bufp[q * 32 + i4];
                    ffma2(g0[q], wa0, cp.x); ffma2(g1[q], wa1, cp.x);
                    ffma2(g2[q], wa2, cp.x);
                    ffma2(g0[q], wb0, cp.y); ffma2(g1[q], wb1, cp.y);
                    ffma2(g2[q], wb2, cp.y);
                }
            }
            __syncwarp();

            #pragma unroll
            for (int q = 0; q < NPW; q++) {
                float ga = psum(g0[q]), gb = psum(g1[q]), gc = psum(g2[q]);
                if (valid[q]) {
                    float* o = out + (size_t)nn[q] * OUTW;
                    o[lane]      = ga;
                    o[32 + lane] = gb;
                    if (lane < 3) o[64 + lane] = gc;
                }
                if (lane >= 3) buf[q * 128 + lane - 3] = ga;
                buf[q * 128 + lane + 29] = gb;
                if (lane < 3) buf[q * 128 + lane + 61] = gc;
            }
            __syncwarp();

            // head: feats(64, aligned) -> 32 relu -> 1 sigmoid
            u64 p0[NPW];
            {
                u64 ii = pack2(sm[OFF_PB1 + lane], 0.f);
                #pragma unroll
                for (int q = 0; q < NPW; q++) p0[q] = ii;
            }
            #pragma unroll 4
            for (int i4 = 0; i4 < 16; i4++) {
                int t0 = 2 * i4, t1 = 2 * i4 + 1;
                u64 w0 = sP1p[t0 * 32 + lane];
                u64 w1 = sP1p[t1 * 32 + lane];
                #pragma unroll
                for (int q = 0; q < NPW; q++) {
                    ulonglong2 cp = bufp[q * 32 + i4];
                    ffma2(p0[q], w0, cp.x);
                    ffma2(p0[q], w1, cp.y);
                }
            }
            float w2s = sm[OFF_P2 + lane];
            float pb2v = sm[OFF_PB2];
            #pragma unroll
            for (int q = 0; q < NPW; q++) {
                float v = fmaxf(psum(p0[q]), 0.f) * w2s;
                #pragma unroll
                for (int o = 16; o > 0; o >>= 1)
                    v += __shfl_xor_sync(0xffffffffu, v, o);
                if (lane == 0 && valid[q])
                    out[(size_t)nn[q] * OUTW + 67] =
                        1.f / (1.f + expf(-(v + pb2v)));
            }
            __syncwarp();
        }
    }
}

// ---------------------------------------------------------------------------
extern "C" void kernel_launch(void* const* d_in, const int* in_sizes, int n_in,
                              void* d_out, int out_size) {
    const float* nf  = (const float*)d_in[0];
    const float* ops = (const float*)d_in[1];
    const int*   ei  = (const int*)d_in[2];
    const float* W1  = (const float*)d_in[3];
    const float* b1  = (const float*)d_in[4];
    const float* W2  = (const float*)d_in[5];
    const float* b2  = (const float*)d_in[6];
    const float* W3  = (const float*)d_in[7];
    const float* b3  = (const float*)d_in[8];
    const float* P1  = (const float*)d_in[9];
    const float* pb1 = (const float*)d_in[10];
    const float* P2  = (const float*)d_in[11];
    const float* pb2 = (const float*)d_in[12];
    float* out = (float*)d_out;

    int E = in_sizes[2] / 2;

    cudaMemsetAsync(d_out, 0, (size_t)out_size * sizeof(float));

    static_assert(SMEM_FLOATS * 4 <= 227 * 1024, "smem");
    cudaFuncSetAttribute(fused_kernel,
                         cudaFuncAttributeMaxDynamicSharedMemorySize,
                         SMEM_FLOATS * 4);
    fused_kernel<<<FB, FT, SMEM_FLOATS * 4>>>(
        nf, ops, ei, E, W1, b1, W2, b2, W3, b3, P1, pb1, P2, pb2, out);
}

// round 12
// speedup vs baseline: 1.1458x; 1.1458x over previous
#include <cuda_runtime.h>
#include <cstdint>

#define N_NODES 100000
#define OUTW 68
typedef unsigned long long u64;

__device__ float g_nsum[(size_t)N_NODES * 64];
__device__ float g_deg[N_NODES];
__device__ unsigned g_pmaskbits[3136];
__device__ int g_list[N_NODES];
__device__ int g_cnt;

__device__ __forceinline__ u64 pack2(float a, float b) {
    u64 r; asm("mov.b64 %0, {%1, %2};" : "=l"(r) : "f"(a), "f"(b)); return r;
}
__device__ __forceinline__ void ffma2(u64& d, u64 a, u64 b) {
    asm("fma.rn.f32x2 %0, %1, %2, %3;" : "=l"(d) : "l"(a), "l"(b), "l"(d));
}
__device__ __forceinline__ float psum(u64 v) {
    float a, b;
    asm("mov.b64 {%0, %1}, %2;" : "=f"(a), "=f"(b) : "l"(v));
    return a + b;
}

// ---------------------------------------------------------------------------
// Kernel 1: softmax gate -> bit mask, zero deg, zero nsum rows of masked nodes
// ---------------------------------------------------------------------------
__global__ void pmask_kernel(const float* __restrict__ ops) {
    int n = blockIdx.x * blockDim.x + threadIdx.x;
    if (n == 0) g_cnt = 0;
    bool msk = false;
    if (n < N_NODES) {
        float o0 = ops[n * 4 + 0], o1 = ops[n * 4 + 1];
        float o2 = ops[n * 4 + 2], o3 = ops[n * 4 + 3];
        float mx = fmaxf(fmaxf(o0, o1), fmaxf(o2, o3));
        float e0 = expf(o0 - mx), e1 = expf(o1 - mx);
        float e2 = expf(o2 - mx), e3 = expf(o3 - mx);
        float p0 = e0 / (e0 + e1 + e2 + e3);
        msk = (p0 > 0.5f);
        g_deg[n] = 0.f;
    }
    unsigned bits = __ballot_sync(0xffffffffu, msk);
    if ((threadIdx.x & 31) == 0 && (n & ~31) < N_NODES)
        g_pmaskbits[n >> 5] = bits;
    if (msk) {
        float4 z = make_float4(0.f, 0.f, 0.f, 0.f);
        float4* row = reinterpret_cast<float4*>(g_nsum) + (size_t)n * 16;
        #pragma unroll
        for (int c = 0; c < 16; c++) row[c] = z;
    }
}

// ---------------------------------------------------------------------------
// Kernel 2: gated edge scatter — ONE thread per edge (index loads once),
// two ballot-redistribution passes (one per direction), 4 jobs/iter.
// ---------------------------------------------------------------------------
__device__ __forceinline__ void scatter_jobs(bool active, int tgt, int srcn,
                                             int lane,
                                             const float4* __restrict__ feat4,
                                             float4* nsum4) {
    unsigned m = __ballot_sync(0xffffffffu, active);
    int grp = lane >> 3;
    int c = lane & 7;
    while (m) {
        int b0 = -1, b1 = -1, b2 = -1, b3 = -1;
        b0 = __ffs(m) - 1; m &= m - 1;
        if (m) { b1 = __ffs(m) - 1; m &= m - 1; }
        if (m) { b2 = __ffs(m) - 1; m &= m - 1; }
        if (m) { b3 = __ffs(m) - 1; m &= m - 1; }
        int myb = (grp == 0) ? b0 : (grp == 1) ? b1 : (grp == 2) ? b2 : b3;
        int bb = (myb >= 0) ? myb : b0;
        int T = __shfl_sync(0xffffffffu, tgt,  bb);
        int S = __shfl_sync(0xffffffffu, srcn, bb);
        if (myb >= 0) {
            float4 v0 = __ldg(&feat4[(size_t)S * 16 + c]);
            float4 v1 = __ldg(&feat4[(size_t)S * 16 + c + 8]);
            asm volatile("red.global.add.v4.f32 [%0], {%1,%2,%3,%4};" ::
                         "l"(nsum4 + (size_t)T * 16 + c),
                         "f"(v0.x), "f"(v0.y), "f"(v0.z), "f"(v0.w) : "memory");
            asm volatile("red.global.add.v4.f32 [%0], {%1,%2,%3,%4};" ::
                         "l"(nsum4 + (size_t)T * 16 + c + 8),
                         "f"(v1.x), "f"(v1.y), "f"(v1.z), "f"(v1.w) : "memory");
            if (c == 0) atomicAdd(&g_deg[T], 1.f);
        }
    }
}

__global__ void edge_kernel(const int* __restrict__ ei,
                            const float4* __restrict__ feat4,
                            int E) {
    int e = blockIdx.x * blockDim.x + threadIdx.x;
    int lane = threadIdx.x & 31;
    bool v = e < E;
    int s = 0, d = 0;
    if (v) { s = __ldg(&ei[e]); d = __ldg(&ei[E + e]); }
    bool a0 = v && ((g_pmaskbits[s >> 5] >> (s & 31)) & 1);
    bool a1 = v && ((g_pmaskbits[d >> 5] >> (d & 31)) & 1);
    float4* nsum4 = reinterpret_cast<float4*>(g_nsum);
    scatter_jobs(a0, s, d, lane, feat4, nsum4);   // tgt=s accumulates feat[d]
    scatter_jobs(a1, d, s, lane, feat4, nsum4);   // tgt=d accumulates feat[s]
}

// ---------------------------------------------------------------------------
// Kernel 3: compact active nodes (warp-aggregated atomic)
// ---------------------------------------------------------------------------
__global__ void compact_kernel() {
    int n = blockIdx.x * blockDim.x + threadIdx.x;
    int lane = threadIdx.x & 31;
    bool act = false;
    if (n < N_NODES)
        act = ((g_pmaskbits[n >> 5] >> (n & 31)) & 1) && (g_deg[n] > 0.f);
    unsigned m = __ballot_sync(0xffffffffu, act);
    int base = 0;
    if (lane == 0 && m) base = atomicAdd(&g_cnt, __popc(m));
    base = __shfl_sync(0xffffffffu, base, 0);
    if (act) g_list[base + __popc(m & ((1u << lane) - 1))] = n;
}

// ---------------------------------------------------------------------------
// Kernel 4: MLP — R10 proven core (K-paired FFMA2, NPW=4, 24 warps).
// ---------------------------------------------------------------------------
#define WARPS 24
#define THREADS (WARPS * 32)
#define NPW 4

#define OFF_W1   0
#define OFF_W2   16384
#define OFF_W3   24576
#define OFF_P1   28928
#define OFF_B1   30976
#define OFF_B2   31104
#define OFF_B3   31168
#define OFF_PB1  31236
#define OFF_P2   31268
#define OFF_PB2  31300
#define OFF_SCR  31304
#define SMEM_FLOATS (OFF_SCR + WARPS * NPW * 128)

__global__ void __launch_bounds__(THREADS, 1)
mlp_kernel(const float* __restrict__ nf,
           const float* __restrict__ W1, const float* __restrict__ b1,
           const float* __restrict__ W2, const float* __restrict__ b2,
           const float* __restrict__ W3, const float* __restrict__ b3,
           const float* __restrict__ P1, const float* __restrict__ pb1,
           const float* __restrict__ P2, const float* __restrict__ pb2,
           float* __restrict__ out) {
    extern __shared__ float sm[];
    int tid = threadIdx.x;

    {
        const float4* W1_4 = reinterpret_cast<const float4*>(W1);
        u64* W1p = reinterpret_cast<u64*>(sm + OFF_W1);
        for (int idx = tid; idx < 2048; idx += THREADS) {
            int t = idx >> 5, jv = idx & 31;
            float4 a = W1_4[(2 * t) * 32 + jv];
            float4 b = W1_4[(2 * t + 1) * 32 + jv];
            ulonglong2* dst = reinterpret_cast<ulonglong2*>(W1p + t * 128 + 4 * jv);
            dst[0] = make_ulonglong2(pack2(a.x, b.x), pack2(a.y, b.y));
            dst[1] = make_ulonglong2(pack2(a.z, b.z), pack2(a.w, b.w));
        }
        const float4* W2_4 = reinterpret_cast<const float4*>(W2);
        u64* W2p = reinterpret_cast<u64*>(sm + OFF_W2);
        for (int idx = tid; idx < 1024; idx += THREADS) {
            int t = idx >> 4, jv = idx & 15;
            float4 a = W2_4[(2 * t) * 16 + jv];
            float4 b = W2_4[(2 * t + 1) * 16 + jv];
            ulonglong2* dst = reinterpret_cast<ulonglong2*>(W2p + t * 64 + 4 * jv);
            dst[0] = make_ulonglong2(pack2(a.x, b.x), pack2(a.y, b.y));
            dst[1] = make_ulonglong2(pack2(a.z, b.z), pack2(a.w, b.w));
        }
        u64* W3p = reinterpret_cast<u64*>(sm + OFF_W3);
        for (int idx = tid; idx < 2176; idx += THREADS) {
            int t = idx / 68, j = idx - t * 68;
            W3p[idx] = (j < 67)
                ? pack2(W3[(2 * t) * 67 + j], W3[(2 * t + 1) * 67 + j]) : 0ull;
        }
        const float4* P1_4 = reinterpret_cast<const float4*>(P1);
        u64* P1p = reinterpret_cast<u64*>(sm + OFF_P1);
        for (int idx = tid; idx < 256; idx += THREADS) {
            int t = idx >> 3, jv = idx & 7;
            float4 a = P1_4[(2 * t) * 8 + jv];
            float4 b = P1_4[(2 * t + 1) * 8 + jv];
            ulonglong2* dst = reinterpret_cast<ulonglong2*>(P1p + t * 32 + 4 * jv);
            dst[0] = make_ulonglong2(pack2(a.x, b.x), pack2(a.y, b.y));
            dst[1] = make_ulonglong2(pack2(a.z, b.z), pack2(a.w, b.w));
        }
    }
    for (int i = tid; i < 128; i += THREADS) sm[OFF_B1 + i] = b1[i];
    for (int i = tid; i < 64;  i += THREADS) sm[OFF_B2 + i] = b2[i];
    for (int i = tid; i < 67;  i += THREADS) sm[OFF_B3 + i] = b3[i];
    for (int i = tid; i < 32;  i += THREADS) sm[OFF_PB1 + i] = pb1[i];
    for (int i = tid; i < 32;  i += THREADS) sm[OFF_P2 + i] = P2[i];
    if (tid == 0) sm[OFF_PB2] = pb2[0];
    __syncthreads();

    int warpId = tid >> 5;
    int lane   = tid & 31;
    float* buf = sm + OFF_SCR + warpId * (NPW * 128);
    float4* buf4 = reinterpret_cast<float4*>(buf);
    ulonglong2* bufp = reinterpret_cast<ulonglong2*>(buf);

    const ulonglong2* sW1p2 = reinterpret_cast<const ulonglong2*>(sm + OFF_W1);
    const ulonglong2* sW2p2 = reinterpret_cast<const ulonglong2*>(sm + OFF_W2);
    const u64*        sW3p  = reinterpret_cast<const u64*>(sm + OFF_W3);
    const u64*        sP1p  = reinterpret_cast<const u64*>(sm + OFF_P1);
    const float4*     sb1_4 = reinterpret_cast<const float4*>(sm + OFF_B1);

    const int cnt = g_cnt;
    const int totalWarps = gridDim.x * WARPS;

    for (int g = blockIdx.x * WARPS + warpId; g * NPW < cnt; g += totalWarps) {
        int nn[NPW];
        bool valid[NPW];
        #pragma unroll
        for (int q = 0; q < NPW; q++) {
            int li = g * NPW + q;
            valid[q] = li < cnt;
            nn[q] = g_list[valid[q] ? li : g * NPW];
        }

        #pragma unroll
        for (int q = 0; q < NPW; q++) {
            int n = nn[q];
            float inv = 1.f / fmaxf(g_deg[n], 1.f);
            buf[q * 128 + lane]      = nf[(size_t)n * 64 + lane];
            buf[q * 128 + 32 + lane] = nf[(size_t)n * 64 + 32 + lane];
            buf[q * 128 + 64 + lane] = g_nsum[(size_t)n * 64 + lane] * inv;
            buf[q * 128 + 96 + lane] = g_nsum[(size_t)n * 64 + 32 + lane] * inv;
        }
        __syncwarp();

        // layer 1: 128 -> 128 relu (K-paired FFMA2)
        u64 a0[NPW], a1[NPW], a2[NPW], a3[NPW];
        {
            float4 bb = sb1_4[lane];
            u64 i0 = pack2(bb.x, 0.f), i1 = pack2(bb.y, 0.f);
            u64 i2 = pack2(bb.z, 0.f), i3 = pack2(bb.w, 0.f);
            #pragma unroll
            for (int q = 0; q < NPW; q++) {
                a0[q] = i0; a1[q] = i1; a2[q] = i2; a3[q] = i3;
            }
        }
        #pragma unroll 4
        for (int i4 = 0; i4 < 32; i4++) {
            int t0 = 2 * i4, t1 = 2 * i4 + 1;
            ulonglong2 wA0 = sW1p2[t0 * 64 + 2 * lane];
            ulonglong2 wA1 = sW1p2[t0 * 64 + 2 * lane + 1];
            ulonglong2 wB0 = sW1p2[t1 * 64 + 2 * lane];
            ulonglong2 wB1 = sW1p2[t1 * 64 + 2 * lane + 1];
            #pragma unroll
            for (int q = 0; q < NPW; q++) {
                ulonglong2 cp = bufp[q * 32 + i4];
                ffma2(a0[q], wA0.x, cp.x); ffma2(a1[q], wA0.y, cp.x);
                ffma2(a2[q], wA1.x, cp.x); ffma2(a3[q], wA1.y, cp.x);
                ffma2(a0[q], wB0.x, cp.y); ffma2(a1[q], wB0.y, cp.y);
                ffma2(a2[q], wB1.x, cp.y); ffma2(a3[q], wB1.y, cp.y);
            }
        }
        __syncwarp();
        #pragma unroll
        for (int q = 0; q < NPW; q++) {
            buf4[q * 32 + lane] = make_float4(
                fmaxf(psum(a0[q]), 0.f), fmaxf(psum(a1[q]), 0.f),
                fmaxf(psum(a2[q]), 0.f), fmaxf(psum(a3[q]), 0.f));
        }
        __syncwarp();

        // layer 2: 128 -> 64 relu
        u64 c0[NPW], c1[NPW];
        {
            u64 i0 = pack2(sm[OFF_B2 + 2 * lane], 0.f);
            u64 i1 = pack2(sm[OFF_B2 + 2 * lane + 1], 0.f);
            #pragma unroll
            for (int q = 0; q < NPW; q++) { c0[q] = i0; c1[q] = i1; }
        }
        #pragma unroll 4
        for (int i4 = 0; i4 < 32; i4++) {
            int t0 = 2 * i4, t1 = 2 * i4 + 1;
            ulonglong2 w0 = sW2p2[t0 * 32 + lane];
            ulonglong2 w1 = sW2p2[t1 * 32 + lane];
            #pragma unroll
            for (int q = 0; q < NPW; q++) {
                ulonglong2 cp = bufp[q * 32 + i4];
                ffma2(c0[q], w0.x, cp.x); ffma2(c1[q], w0.y, cp.x);
                ffma2(c0[q], w1.x, cp.y); ffma2(c1[q], w1.y, cp.y);
            }
        }
        __syncwarp();
        #pragma unroll
        for (int q = 0; q < NPW; q++) {
            reinterpret_cast<float2*>(buf)[q * 64 + lane] = make_float2(
                fmaxf(psum(c0[q]), 0.f), fmaxf(psum(c1[q]), 0.f));
        }
        __syncwarp();

        // layer 3: 64 -> 67
        u64 g0[NPW], g1[NPW], g2[NPW];
        {
            u64 i0 = pack2(sm[OFF_B3 + lane], 0.f);
            u64 i1 = pack2(sm[OFF_B3 + 32 + lane], 0.f);
            u64 i2 = (lane < 3) ? pack2(sm[OFF_B3 + 64 + lane], 0.f) : 0ull;
            #pragma unroll
            for (int q = 0; q < NPW; q++) { g0[q] = i0; g1[q] = i1; g2[q] = i2; }
        }
        #pragma unroll 4
        for (int i4 = 0; i4 < 16; i4++) {
            int t0 = 2 * i4, t1 = 2 * i4 + 1;
            u64 wa0 = sW3p[t0 * 68 + lane];
            u64 wa1 = sW3p[t0 * 68 + 32 + lane];
            u64 wa2 = (lane < 3) ? sW3p[t0 * 68 + 64 + lane] : 0ull;
            u64 wb0 = sW3p[t1 * 68 + lane];
            u64 wb1 = sW3p[t1 * 68 + 32 + lane];
            u64 wb2 = (lane < 3) ? sW3p[t1 * 68 + 64 + lane] : 0ull;
            #pragma unroll
            for (int q = 0; q < NPW; q++) {
                ulonglong2 cp = bufp[q * 32 + i4];
                ffma2(g0[q], wa0, cp.x); ffma2(g1[q], wa1, cp.x);
                ffma2(g2[q], wa2, cp.x);
                ffma2(g0[q], wb0, cp.y); ffma2(g1[q], wb1, cp.y);
                ffma2(g2[q], wb2, cp.y);
            }
        }
        __syncwarp();

        #pragma unroll
        for (int q = 0; q < NPW; q++) {
            float ga = psum(g0[q]), gb = psum(g1[q]), gc = psum(g2[q]);
            if (valid[q]) {
                float* o = out + (size_t)nn[q] * OUTW;
                o[lane]      = ga;
                o[32 + lane] = gb;
                if (lane < 3) o[64 + lane] = gc;
            }
            if (lane >= 3) buf[q * 128 + lane - 3] = ga;
            buf[q * 128 + lane + 29] = gb;
            if (lane < 3) buf[q * 128 + lane + 61] = gc;
        }
        __syncwarp();

        // head: feats(64, aligned) -> 32 relu -> 1 sigmoid
        u64 p0[NPW];
        {
            u64 ii = pack2(sm[OFF_PB1 + lane], 0.f);
            #pragma unroll
            for (int q = 0; q < NPW; q++) p0[q] = ii;
        }
        #pragma unroll 4
        for (int i4 = 0; i4 < 16; i4++) {
            int t0 = 2 * i4, t1 = 2 * i4 + 1;
            u64 w0 = sP1p[t0 * 32 + lane];
            u64 w1 = sP1p[t1 * 32 + lane];
            #pragma unroll
            for (int q = 0; q < NPW; q++) {
                ulonglong2 cp = bufp[q * 32 + i4];
                ffma2(p0[q], w0, cp.x);
                ffma2(p0[q], w1, cp.y);
            }
        }
        float w2s = sm[OFF_P2 + lane];
        float pb2v = sm[OFF_PB2];
        #pragma unroll
        for (int q = 0; q < NPW; q++) {
            float v = fmaxf(psum(p0[q]), 0.f) * w2s;
            #pragma unroll
            for (int o = 16; o > 0; o >>= 1)
                v += __shfl_xor_sync(0xffffffffu, v, o);
            if (lane == 0 && valid[q])
                out[(size_t)nn[q] * OUTW + 67] =
                    1.f / (1.f + expf(-(v + pb2v)));
        }
        __syncwarp();
    }
}

// ---------------------------------------------------------------------------
extern "C" void kernel_launch(void* const* d_in, const int* in_sizes, int n_in,
                              void* d_out, int out_size) {
    const float* nf  = (const float*)d_in[0];
    const float* ops = (const float*)d_in[1];
    const int*   ei  = (const int*)d_in[2];
    const float* W1  = (const float*)d_in[3];
    const float* b1  = (const float*)d_in[4];
    const float* W2  = (const float*)d_in[5];
    const float* b2  = (const float*)d_in[6];
    const float* W3  = (const float*)d_in[7];
    const float* b3  = (const float*)d_in[8];
    const float* P1  = (const float*)d_in[9];
    const float* pb1 = (const float*)d_in[10];
    const float* P2  = (const float*)d_in[11];
    const float* pb2 = (const float*)d_in[12];
    float* out = (float*)d_out;

    int E = in_sizes[2] / 2;

    cudaMemsetAsync(d_out, 0, (size_t)out_size * sizeof(float));

    pmask_kernel<<<(N_NODES + 255) / 256, 256>>>(ops);

    edge_kernel<<<(E + 255) / 256, 256>>>(ei, (const float4*)nf, E);

    compact_kernel<<<(N_NODES + 255) / 256, 256>>>();

    static_assert(SMEM_FLOATS * 4 <= 227 * 1024, "smem");
    cudaFuncSetAttribute(mlp_kernel,
                         cudaFuncAttributeMaxDynamicSharedMemorySize,
                         SMEM_FLOATS * 4);
    mlp_kernel<<<152, THREADS, SMEM_FLOATS * 4>>>(
        nf, W1, b1, W2, b2, W3, b3, P1, pb1, P2, pb2, out);
}